// round 15
// baseline (speedup 1.0000x reference)
#include <cuda_runtime.h>
#include <cuda_fp16.h>
#include <math.h>

// Problem constants
#define BB 2
#define SS 1024
#define DD 768
#define HH 12
#define DKK 64
#define DFFF 3072
#define VV 32000
#define LL 4
#define MM (BB*SS)       // 2048
#define NQKV (3*DD)      // 2304

// ---------------- scratch (static device globals; no allocation) -------------
__device__ float  g_h    [MM*DD];
__device__ float  g_tmp  [MM*DD];
__device__ __half g_h16  [MM*DD];
__device__ __half g_qkv16[MM*NQKV];
__device__ __half g_av16 [MM*DD];
__device__ __half g_ff16 [MM*DFFF];
// attention split-kv partials (fp32), 4 parities
__device__ float  g_avp [4*MM*DD];
__device__ float  g_den [4*MM*HH];
// fp16 weights
__device__ __half g_wqkv16[LL*DD*NQKV];   // packed [l][k][which*768+n]
__device__ __half g_wo16  [LL*DD*DD];
__device__ __half g_w116  [LL*DD*DFFF];
__device__ __half g_w216  [LL*DFFF*DD];
__device__ __half g_lm16  [DD*VV];

// ---------------- fp32 -> fp16 weight conversion (MLP=4) ---------------------
#define NQ_QKV (LL*DD*NQKV/4)
#define NQ_WO  (LL*DD*DD/4)
#define NQ_W1  (LL*DD*DFFF/4)
#define NQ_W2  (LL*DFFF*DD/4)
#define NQ_LM  (DD*VV/4)
#define NC_QKV (NQ_QKV/4)
#define NC_WO  (NQ_WO/4)
#define NC_W1  (NQ_W1/4)
#define NC_W2  (NQ_W2/4)
#define NC_LM  (NQ_LM/4)
#define NC_LAYERS (NC_QKV+NC_WO+NC_W1+NC_W2)

// layer weights only (runs synchronously, small)
__global__ void convert_layers(const float* __restrict__ Wq, const float* __restrict__ Wk,
                               const float* __restrict__ Wv, const float* __restrict__ Wo,
                               const float* __restrict__ W1, const float* __restrict__ W2,
                               __half2* __restrict__ dqkv, __half2* __restrict__ dwo,
                               __half2* __restrict__ dw1, __half2* __restrict__ dw2) {
    long long i = (long long)blockIdx.x * blockDim.x + threadIdx.x;
    const float* src;
    __half2* dst;
    if (i < NC_QKV) {
        long long e = i * 16;
        int c = (int)(e % NQKV);
        int k = (int)((e / NQKV) % DD);
        int l = (int)(e / ((long long)NQKV * DD));
        int which = c / DD;
        int n = c % DD;
        const float* W = (which == 0) ? Wq : (which == 1) ? Wk : Wv;
        src = W + (size_t)l * DD * DD + (size_t)k * DD + n;
        dst = dqkv + e / 2;
    }
    else if ((i -= NC_QKV) < NC_WO)      { src = Wo + i * 16; dst = dwo + i * 8; }
    else if ((i -= NC_WO)  < NC_W1)      { src = W1 + i * 16; dst = dw1 + i * 8; }
    else if ((i -= NC_W1)  < NC_W2)      { src = W2 + i * 16; dst = dw2 + i * 8; }
    else return;

    float4 v0 = *reinterpret_cast<const float4*>(src + 0);
    float4 v1 = *reinterpret_cast<const float4*>(src + 4);
    float4 v2 = *reinterpret_cast<const float4*>(src + 8);
    float4 v3 = *reinterpret_cast<const float4*>(src + 12);
    __half2 h[8];
    h[0] = __floats2half2_rn(v0.x, v0.y); h[1] = __floats2half2_rn(v0.z, v0.w);
    h[2] = __floats2half2_rn(v1.x, v1.y); h[3] = __floats2half2_rn(v1.z, v1.w);
    h[4] = __floats2half2_rn(v2.x, v2.y); h[5] = __floats2half2_rn(v2.z, v2.w);
    h[6] = __floats2half2_rn(v3.x, v3.y); h[7] = __floats2half2_rn(v3.z, v3.w);
    reinterpret_cast<uint4*>(dst)[0] = reinterpret_cast<uint4*>(h)[0];
    reinterpret_cast<uint4*>(dst)[1] = reinterpret_cast<uint4*>(h)[1];
}

// LM-head weight (runs on side stream, overlapped with the layer stack)
__global__ void convert_lm(const float* __restrict__ lm_W, __half2* __restrict__ dlm) {
    long long i = (long long)blockIdx.x * blockDim.x + threadIdx.x;
    if (i >= NC_LM) return;
    const float* src = lm_W + i * 16;
    __half2* dst = dlm + i * 8;
    float4 v0 = *reinterpret_cast<const float4*>(src + 0);
    float4 v1 = *reinterpret_cast<const float4*>(src + 4);
    float4 v2 = *reinterpret_cast<const float4*>(src + 8);
    float4 v3 = *reinterpret_cast<const float4*>(src + 12);
    __half2 h[8];
    h[0] = __floats2half2_rn(v0.x, v0.y); h[1] = __floats2half2_rn(v0.z, v0.w);
    h[2] = __floats2half2_rn(v1.x, v1.y); h[3] = __floats2half2_rn(v1.z, v1.w);
    h[4] = __floats2half2_rn(v2.x, v2.y); h[5] = __floats2half2_rn(v2.z, v2.w);
    h[6] = __floats2half2_rn(v3.x, v3.y); h[7] = __floats2half2_rn(v3.z, v3.w);
    reinterpret_cast<uint4*>(dst)[0] = reinterpret_cast<uint4*>(h)[0];
    reinterpret_cast<uint4*>(dst)[1] = reinterpret_cast<uint4*>(h)[1];
}

// ---------------- embedding + sinusoidal PE ----------------------------------
__global__ void embed_kernel(const int* __restrict__ x, const float* __restrict__ emb,
                             float* __restrict__ h, __half* __restrict__ h16) {
    int row = blockIdx.x;
    int s = row & (SS - 1);
    int tok = x[row];
    const float L2E = 13.287712379549449f;   // log2(10000)
    for (int c = threadIdx.x; c < DD; c += blockDim.x) {
        float ef = (float)(c & ~1) / (float)DD;
        float inv_sc = exp2f(-ef * L2E);
        float ang = (float)s * inv_sc;
        float pe = (c & 1) ? cosf(ang) : sinf(ang);
        float v = emb[(size_t)tok * DD + c] + pe;
        h[(size_t)row * DD + c] = v;
        h16[(size_t)row * DD + c] = __float2half(v);
    }
}

// ---------------- common PTX helpers -----------------------------------------
__device__ __forceinline__ float gelu_exact(float x) {
    return 0.5f * x * (1.0f + erff(x * 0.7071067811865476f));
}

#define CPA16(dst, src) asm volatile("cp.async.cg.shared.global [%0], [%1], 16;" :: "r"(dst), "l"(src))
#define LDSM4(r0,r1,r2,r3,addr) \
    asm volatile("ldmatrix.sync.aligned.m8n8.x4.shared.b16 {%0,%1,%2,%3},[%4];" \
                 : "=r"(r0),"=r"(r1),"=r"(r2),"=r"(r3) : "r"(addr))
#define LDSM4T(r0,r1,r2,r3,addr) \
    asm volatile("ldmatrix.sync.aligned.m8n8.x4.trans.shared.b16 {%0,%1,%2,%3},[%4];" \
                 : "=r"(r0),"=r"(r1),"=r"(r2),"=r"(r3) : "r"(addr))

__device__ __forceinline__ void mma16816(float c[4], const unsigned a[4], const unsigned b[2]) {
    asm volatile("mma.sync.aligned.m16n8k16.row.col.f32.f16.f16.f32 "
                 "{%0,%1,%2,%3},{%4,%5,%6,%7},{%8,%9},{%0,%1,%2,%3};"
                 : "+f"(c[0]), "+f"(c[1]), "+f"(c[2]), "+f"(c[3])
                 : "r"(a[0]), "r"(a[1]), "r"(a[2]), "r"(a[3]), "r"(b[0]), "r"(b[1]));
}

__device__ __forceinline__ unsigned cvta_s(const void* p) {
    return (unsigned)__cvta_generic_to_shared(p);
}
__device__ __forceinline__ unsigned packh2(float x, float y) {
    __half2 h = __floats2half2_rn(x, y);
    return *reinterpret_cast<unsigned*>(&h);
}

// ---------------- fp16 tensor-core GEMM: BMxBN tiles, 4-stage cp.async -------
#define ASTR 40
#define NST 4
#define SMEM_GEMM_BYTES(BM,BN) ((NST*((BM)*ASTR + 32*((BN)+8))) * 2)

template<int BM, int BN, typename OutT>
__device__ __forceinline__ void gemm_body(
    const __half* __restrict__ A, const __half* __restrict__ B,
    const float* __restrict__ bias, OutT* __restrict__ C,
    int N, int K, int epi, int bx, int by, __half* sm)
{
    constexpr int MT = BM / 32;
    constexpr int NJ = BN / 32;
    constexpr int BSTR = BN + 8;
    constexpr int ABUF_H = BM * ASTR;
    constexpr int BBUF_H = 32 * BSTR;

    __half* As = sm;
    __half* Bs = sm + NST * ABUF_H;

    int tid = threadIdx.x;
    int lane = tid & 31;
    int warp = tid >> 5;
    int wm = warp >> 2;
    int wn = warp & 3;
    int g  = lane >> 2;
    int tg = lane & 3;

    const __half* Ab = A + (size_t)by * BM * K;
    const __half* Bb = B + (size_t)bx * BN;

    float c[MT][NJ][4];
    #pragma unroll
    for (int i = 0; i < MT; i++)
        #pragma unroll
        for (int j = 0; j < NJ; j++)
            #pragma unroll
            for (int r = 0; r < 4; r++) c[i][j][r] = 0.f;

    const int T = K >> 5;

    auto load_tile = [&](int kt, int buf) {
        __half* Ad = As + buf * ABUF_H;
        __half* Bd = Bs + buf * BBUF_H;
        #pragma unroll
        for (int i = 0; i < BM / 64; i++) {
            int s = tid + i * 256;
            int r  = s >> 2;
            int k8 = (s & 3) * 8;
            unsigned dst = cvta_s(Ad + r * ASTR + k8);
            CPA16(dst, Ab + (size_t)r * K + kt + k8);
        }
        #pragma unroll
        for (int i = 0; i < BN / 64; i++) {
            int s = tid + i * 256;
            int r  = s / (BN / 8);
            int n8 = (s % (BN / 8)) * 8;
            unsigned dst = cvta_s(Bd + r * BSTR + n8);
            CPA16(dst, Bb + (size_t)(kt + r) * N + n8);
        }
    };

    #pragma unroll
    for (int s = 0; s < NST - 1; s++) {
        load_tile(s * 32, s);
        asm volatile("cp.async.commit_group;");
    }

    unsigned aBase = cvta_s(As + (wm * (BM / 2) + (lane & 15)) * ASTR + (lane >> 4) * 8);
    unsigned bBase = cvta_s(Bs + (lane & 15) * BSTR + wn * (BN / 4) + (lane >> 4) * 8);

    for (int t = 0; t < T; t++) {
        asm volatile("cp.async.wait_group %0;" :: "n"(NST - 2));
        __syncthreads();

        int lt = t + NST - 1;
        if (lt < T) load_tile(lt * 32, lt & (NST - 1));
        asm volatile("cp.async.commit_group;");

        int st = t & (NST - 1);
        unsigned aB = aBase + st * (ABUF_H * 2);
        unsigned bB = bBase + st * (BBUF_H * 2);

        #pragma unroll
        for (int kb = 0; kb < 2; kb++) {
            unsigned a[MT][4], b[NJ][2];
            #pragma unroll
            for (int mt = 0; mt < MT; mt++) {
                LDSM4(a[mt][0], a[mt][1], a[mt][2], a[mt][3],
                      aB + (mt * 16 * ASTR + kb * 16) * 2);
            }
            #pragma unroll
            for (int nb = 0; nb < NJ / 2; nb++) {
                unsigned t0, t1, t2, t3;
                LDSM4T(t0, t1, t2, t3, bB + (kb * 16 * BSTR + nb * 16) * 2);
                b[2 * nb][0] = t0; b[2 * nb][1] = t1;
                b[2 * nb + 1][0] = t2; b[2 * nb + 1][1] = t3;
            }
            #pragma unroll
            for (int mt = 0; mt < MT; mt++)
                #pragma unroll
                for (int j = 0; j < NJ; j++)
                    mma16816(c[mt][j], a[mt], b[j]);
        }
    }

    int colg = bx * BN + wn * (BN / 4);
    int rowg = by * BM + wm * (BM / 2);
    #pragma unroll
    for (int mt = 0; mt < MT; mt++) {
        #pragma unroll
        for (int half = 0; half < 2; half++) {
            int row = rowg + mt * 16 + g + half * 8;
            #pragma unroll
            for (int j = 0; j < NJ; j++) {
                int col = colg + j * 8 + tg * 2;
                float v0 = c[mt][j][half * 2 + 0];
                float v1 = c[mt][j][half * 2 + 1];
                if (epi >= 1) { v0 += bias[col]; v1 += bias[col + 1]; }
                if (epi == 2) { v0 = gelu_exact(v0); v1 = gelu_exact(v1); }
                if constexpr (sizeof(OutT) == 4) {
                    float2 w; w.x = v0; w.y = v1;
                    *reinterpret_cast<float2*>((float*)C + (size_t)row * N + col) = w;
                } else {
                    *reinterpret_cast<__half2*>((__half*)C + (size_t)row * N + col) =
                        __floats2half2_rn(v0, v1);
                }
            }
        }
    }
}

template<int BM, int BN, typename OutT, int OCC, bool SWAPG = false>
__global__ __launch_bounds__(256, OCC)
void gemm_f16(const __half* __restrict__ A, const __half* __restrict__ B,
              const float* __restrict__ bias, OutT* __restrict__ C,
              int N, int K, int epi)
{
    extern __shared__ __half smh[];
    int bx = SWAPG ? blockIdx.y : blockIdx.x;
    int by = SWAPG ? blockIdx.x : blockIdx.y;
    gemm_body<BM, BN, OutT>(A, B, bias, C, N, K, epi, bx, by, smh);
}

// ---------------- fp16 TC causal attention, 4-way kv split -------------------
#define QSTR 72
#define KVBUF (64*QSTR)
#define ATTN_SMEM_BYTES (5 * KVBUF * 2)

__global__ __launch_bounds__(128, 4)
void attn_f16(const __half* __restrict__ qkv,
              float* __restrict__ avp, float* __restrict__ den) {
    extern __shared__ __half smh[];
    __half* Qs = smh;
    __half* Ks = smh + KVBUF;
    __half* Vs = smh + 3 * KVBUF;

    int bx = blockIdx.x;
    int qt = 15 - (bx >> 2);
    int parity = bx & 3;
    float* avP  = avp + (size_t)parity * MM * DD;
    float* denP = den + (size_t)parity * MM * HH;

    int bh = blockIdx.y;
    int b = bh / HH, hh = bh % HH;
    const __half* qb = qkv + (size_t)b * SS * NQKV + hh * DKK;
    const __half* kb = qb + DD;
    const __half* vb = qb + 2 * DD;

    int tid = threadIdx.x;
    int lane = tid & 31;
    int warp = tid >> 5;
    int g  = lane >> 2;
    int tg = lane & 3;

    int qg0 = qt * 64 + warp * 16 + g;
    int row0 = b * SS + qg0;
    const int niter = (qt >= parity) ? ((qt - parity) >> 2) + 1 : 0;

    if (niter == 0) {
        #pragma unroll
        for (int nb = 0; nb < 8; nb++) {
            int col = hh * DKK + nb * 8 + 2 * tg;
            float2 z; z.x = 0.f; z.y = 0.f;
            *reinterpret_cast<float2*>(avP + (size_t)row0 * DD + col) = z;
            *reinterpret_cast<float2*>(avP + (size_t)(row0 + 8) * DD + col) = z;
        }
        if (tg == 0) {
            denP[(size_t)row0 * HH + hh] = 0.f;
            denP[(size_t)(row0 + 8) * HH + hh] = 0.f;
        }
        return;
    }

    #pragma unroll
    for (int i = 0; i < 4; i++) {
        int s = tid + i * 128;
        int r = s >> 3;
        int c8 = (s & 7) * 8;
        CPA16(cvta_s(Qs + r * QSTR + c8), qb + (size_t)(qt * 64 + r) * NQKV + c8);
    }
    auto load_kv = [&](int kt, int buf) {
        __half* Kd = Ks + buf * KVBUF;
        __half* Vd = Vs + buf * KVBUF;
        #pragma unroll
        for (int i = 0; i < 4; i++) {
            int s = tid + i * 128;
            int r = s >> 3;
            int c8 = (s & 7) * 8;
            CPA16(cvta_s(Kd + r * QSTR + c8), kb + (size_t)(kt * 64 + r) * NQKV + c8);
            CPA16(cvta_s(Vd + r * QSTR + c8), vb + (size_t)(kt * 64 + r) * NQKV + c8);
        }
    };
    load_kv(parity, 0);
    asm volatile("cp.async.commit_group;");

    float oacc[8][4];
    #pragma unroll
    for (int i = 0; i < 8; i++)
        #pragma unroll
        for (int j = 0; j < 4; j++) oacc[i][j] = 0.f;
    float den0 = 0.f, den1 = 0.f;

    unsigned qAddr = cvta_s(Qs + (warp * 16 + (lane & 15)) * QSTR + (lane >> 4) * 8);

    for (int it = 0; it < niter; it++) {
        int kt = parity + 4 * it;
        asm volatile("cp.async.wait_group 0;");
        __syncthreads();
        if (it + 1 < niter) {
            load_kv(kt + 4, (it + 1) & 1);
            asm volatile("cp.async.commit_group;");
        }
        const __half* Kb_ = Ks + (it & 1) * KVBUF;
        const __half* Vb_ = Vs + (it & 1) * KVBUF;

        float s[8][4];
        #pragma unroll
        for (int i = 0; i < 8; i++)
            #pragma unroll
            for (int j = 0; j < 4; j++) s[i][j] = 0.f;

        #pragma unroll
        for (int kbk = 0; kbk < 4; kbk++) {
            unsigned a[4];
            LDSM4(a[0], a[1], a[2], a[3], qAddr + kbk * 16 * 2);
            #pragma unroll
            for (int nb2 = 0; nb2 < 4; nb2++) {
                unsigned r0, r1, r2, r3;
                LDSM4(r0, r1, r2, r3,
                      cvta_s(Kb_ + (nb2 * 16 + (lane & 15)) * QSTR + kbk * 16 + (lane >> 4) * 8));
                unsigned b0[2] = { r0, r2 };
                unsigned b1[2] = { r1, r3 };
                mma16816(s[2 * nb2],     a, b0);
                mma16816(s[2 * nb2 + 1], a, b1);
            }
        }

        bool diag = (kt == qt);
        #pragma unroll
        for (int nb = 0; nb < 8; nb++) {
            int kg = kt * 64 + nb * 8 + 2 * tg;
            float e0 = (!diag || kg     < qg0)     ? __expf(s[nb][0] * 0.125f) : 0.f;
            float e1 = (!diag || kg + 1 < qg0)     ? __expf(s[nb][1] * 0.125f) : 0.f;
            float e2 = (!diag || kg     < qg0 + 8) ? __expf(s[nb][2] * 0.125f) : 0.f;
            float e3 = (!diag || kg + 1 < qg0 + 8) ? __expf(s[nb][3] * 0.125f) : 0.f;
            s[nb][0] = e0; s[nb][1] = e1; s[nb][2] = e2; s[nb][3] = e3;
            den0 += e0 + e1;
            den1 += e2 + e3;
        }

        #pragma unroll
        for (int kbk = 0; kbk < 4; kbk++) {
            unsigned a[4];
            a[0] = packh2(s[2 * kbk][0],     s[2 * kbk][1]);
            a[1] = packh2(s[2 * kbk][2],     s[2 * kbk][3]);
            a[2] = packh2(s[2 * kbk + 1][0], s[2 * kbk + 1][1]);
            a[3] = packh2(s[2 * kbk + 1][2], s[2 * kbk + 1][3]);
            #pragma unroll
            for (int nb2 = 0; nb2 < 4; nb2++) {
                unsigned t0, t1, t2, t3;
                LDSM4T(t0, t1, t2, t3,
                       cvta_s(Vb_ + (kbk * 16 + (lane & 15)) * QSTR + nb2 * 16 + (lane >> 4) * 8));
                unsigned b0[2] = { t0, t1 };
                unsigned b1[2] = { t2, t3 };
                mma16816(oacc[2 * nb2],     a, b0);
                mma16816(oacc[2 * nb2 + 1], a, b1);
            }
        }
    }

    den0 += __shfl_xor_sync(0xffffffffu, den0, 1);
    den0 += __shfl_xor_sync(0xffffffffu, den0, 2);
    den1 += __shfl_xor_sync(0xffffffffu, den1, 1);
    den1 += __shfl_xor_sync(0xffffffffu, den1, 2);

    #pragma unroll
    for (int nb = 0; nb < 8; nb++) {
        int col = hh * DKK + nb * 8 + 2 * tg;
        float2 w0; w0.x = oacc[nb][0]; w0.y = oacc[nb][1];
        float2 w1; w1.x = oacc[nb][2]; w1.y = oacc[nb][3];
        *reinterpret_cast<float2*>(avP + (size_t)row0 * DD + col) = w0;
        *reinterpret_cast<float2*>(avP + (size_t)(row0 + 8) * DD + col) = w1;
    }
    if (tg == 0) {
        denP[(size_t)row0 * HH + hh] = den0;
        denP[(size_t)(row0 + 8) * HH + hh] = den1;
    }
}

// combine partials: av16 = (Σp)/(Σd + 1e-9)
__global__ void attn_norm(const float* __restrict__ p, const float* __restrict__ d,
                          __half* __restrict__ o) {
    int row = blockIdx.x;
    size_t base = (size_t)row * DD;
    for (int c = threadIdx.x; c < DD; c += blockDim.x) {
        int hh = c >> 6;
        size_t di = (size_t)row * HH + hh;
        float den = d[di] + d[MM*HH + di] + d[2*(size_t)MM*HH + di] + d[3*(size_t)MM*HH + di] + 1e-9f;
        float num = p[base + c] + p[MM*(size_t)DD + base + c]
                  + p[2*(size_t)MM*DD + base + c] + p[3*(size_t)MM*DD + base + c];
        o[base + c] = __float2half(num / den);
    }
}

// ---------------- warp-per-row residual-add + LayerNorm ----------------------
__global__ __launch_bounds__(256)
void ln_kernel(float* __restrict__ h, const float* __restrict__ delta,
               const float* __restrict__ gs, const float* __restrict__ gb,
               __half* __restrict__ h16) {
    int lane = threadIdx.x & 31;
    int row = blockIdx.x * 8 + (threadIdx.x >> 5);
    size_t base = (size_t)row * DD;
    const float4* hp = reinterpret_cast<const float4*>(h + base);
    const float4* dp = reinterpret_cast<const float4*>(delta + base);

    float4 v[6];
    float sum = 0.f;
    #pragma unroll
    for (int t = 0; t < 6; t++) {
        float4 a = hp[lane + t * 32];
        float4 b = dp[lane + t * 32];
        v[t].x = a.x + b.x; v[t].y = a.y + b.y;
        v[t].z = a.z + b.z; v[t].w = a.w + b.w;
        sum += v[t].x + v[t].y + v[t].z + v[t].w;
    }
    #pragma unroll
    for (int o = 16; o; o >>= 1) sum += __shfl_xor_sync(0xffffffffu, sum, o);
    float mean = sum * (1.0f / 768.0f);

    float sq = 0.f;
    #pragma unroll
    for (int t = 0; t < 6; t++) {
        float dx = v[t].x - mean, dy = v[t].y - mean;
        float dz = v[t].z - mean, dw = v[t].w - mean;
        sq += dx * dx + dy * dy + dz * dz + dw * dw;
    }
    #pragma unroll
    for (int o = 16; o; o >>= 1) sq += __shfl_xor_sync(0xffffffffu, sq, o);
    float inv = rsqrtf(sq * (1.0f / 768.0f) + 1e-5f);

    float4* ho = reinterpret_cast<float4*>(h + base);
    #pragma unroll
    for (int t = 0; t < 6; t++) {
        int c4 = (lane + t * 32) * 4;
        float4 gsv = *reinterpret_cast<const float4*>(gs + c4);
        float4 gbv = *reinterpret_cast<const float4*>(gb + c4);
        float4 r;
        r.x = (v[t].x - mean) * inv * gsv.x + gbv.x;
        r.y = (v[t].y - mean) * inv * gsv.y + gbv.y;
        r.z = (v[t].z - mean) * inv * gsv.z + gbv.z;
        r.w = (v[t].w - mean) * inv * gsv.w + gbv.w;
        ho[lane + t * 32] = r;
        __half2 p0 = __floats2half2_rn(r.x, r.y);
        __half2 p1 = __floats2half2_rn(r.z, r.w);
        __half2* h16o = reinterpret_cast<__half2*>(h16 + base + c4);
        h16o[0] = p0;
        h16o[1] = p1;
    }
}

// ---------------- launcher ---------------------------------------------------
extern "C" void kernel_launch(void* const* d_in, const int* in_sizes, int n_in,
                              void* d_out, int out_size) {
    const int*   x     = (const int*)  d_in[0];
    const float* emb   = (const float*)d_in[1];
    const float* Wq    = (const float*)d_in[2];
    const float* Wk    = (const float*)d_in[3];
    const float* Wv    = (const float*)d_in[4];
    const float* Wo    = (const float*)d_in[5];
    const float* ln1_s = (const float*)d_in[6];
    const float* ln1_b = (const float*)d_in[7];
    const float* W1    = (const float*)d_in[8];
    const float* b1    = (const float*)d_in[9];
    const float* W2    = (const float*)d_in[10];
    const float* b2    = (const float*)d_in[11];
    const float* ln2_s = (const float*)d_in[12];
    const float* ln2_b = (const float*)d_in[13];
    const float* lm_W  = (const float*)d_in[14];
    const float* lm_b  = (const float*)d_in[15];
    float* out = (float*)d_out;

    float *h_, *tmp_, *avp_, *den_;
    __half *h16_, *qkv16_, *av16_, *ff16_, *wqkv16_, *wo16_, *w116_, *w216_, *lm16_;
    cudaGetSymbolAddress((void**)&h_,     g_h);
    cudaGetSymbolAddress((void**)&tmp_,   g_tmp);
    cudaGetSymbolAddress((void**)&avp_,   g_avp);
    cudaGetSymbolAddress((void**)&den_,   g_den);
    cudaGetSymbolAddress((void**)&h16_,   g_h16);
    cudaGetSymbolAddress((void**)&qkv16_, g_qkv16);
    cudaGetSymbolAddress((void**)&av16_,  g_av16);
    cudaGetSymbolAddress((void**)&ff16_,  g_ff16);
    cudaGetSymbolAddress((void**)&wqkv16_, g_wqkv16);
    cudaGetSymbolAddress((void**)&wo16_,   g_wo16);
    cudaGetSymbolAddress((void**)&w116_,   g_w116);
    cudaGetSymbolAddress((void**)&w216_,   g_w216);
    cudaGetSymbolAddress((void**)&lm16_,   g_lm16);

    const int SM128 = SMEM_GEMM_BYTES(128, 128);
    const int SM64  = SMEM_GEMM_BYTES(64, 64);
    cudaFuncSetAttribute(attn_f16, cudaFuncAttributeMaxDynamicSharedMemorySize, ATTN_SMEM_BYTES);
    cudaFuncSetAttribute((const void*)gemm_f16<128, 128, float, 2, true>,   cudaFuncAttributeMaxDynamicSharedMemorySize, SM128);
    cudaFuncSetAttribute((const void*)gemm_f16<128, 128, __half, 2, false>, cudaFuncAttributeMaxDynamicSharedMemorySize, SM128);
    cudaFuncSetAttribute((const void*)gemm_f16<64, 64, float, 3, false>,    cudaFuncAttributeMaxDynamicSharedMemorySize, SM64);

    // side stream + events for overlapping the LM-head conversion
    cudaStream_t s1;
    cudaStreamCreateWithFlags(&s1, cudaStreamNonBlocking);
    cudaEvent_t ev0, ev1;
    cudaEventCreateWithFlags(&ev0, cudaEventDisableTiming);
    cudaEventCreateWithFlags(&ev1, cudaEventDisableTiming);

    // fork: LM-head conversion overlaps with the whole layer stack
    cudaEventRecord(ev0, 0);
    cudaStreamWaitEvent(s1, ev0, 0);
    convert_lm<<<(int)((NC_LM + 255) / 256), 256, 0, s1>>>(lm_W, (__half2*)lm16_);
    cudaEventRecord(ev1, s1);

    // layer weights (synchronous on main stream)
    convert_layers<<<(int)((NC_LAYERS + 255) / 256), 256>>>(
        Wq, Wk, Wv, Wo, W1, W2,
        (__half2*)wqkv16_, (__half2*)wo16_, (__half2*)w116_, (__half2*)w216_);

    embed_kernel<<<MM, 256>>>(x, emb, h_, h16_);

    dim3 gQKV(NQKV / 128, MM / 128);    // (18,16)
    dim3 gN768(DD / 64, MM / 64);       // (12,32) 64x64 tiles
    dim3 gFF1(DFFF / 128, MM / 128);    // (24,16)
    dim3 gLM(MM / 128, VV / 128);       // (16,250) swapped: M fastest
    dim3 gAttn(64, BB * HH);            // (64,24): (qt, 4-way parity)

    for (int l = 0; l < LL; l++) {
        const __half* wqkv_l = wqkv16_ + (size_t)l * DD * NQKV;
        const __half* wo_l   = wo16_   + (size_t)l * DD * DD;
        const __half* w1_l   = w116_   + (size_t)l * DD * DFFF;
        const __half* w2_l   = w216_   + (size_t)l * DFFF * DD;

        gemm_f16<128, 128, __half, 2><<<gQKV, 256, SM128>>>(h16_, wqkv_l, nullptr, qkv16_, NQKV, DD, 0);

        attn_f16<<<gAttn, 128, ATTN_SMEM_BYTES>>>(qkv16_, avp_, den_);
        attn_norm<<<MM, 256>>>(avp_, den_, av16_);

        gemm_f16<64, 64, float, 3><<<gN768, 256, SM64>>>(av16_, wo_l, nullptr, tmp_, DD, DD, 0);
        ln_kernel<<<MM / 8, 256>>>(h_, tmp_, ln1_s + (size_t)l * DD, ln1_b + (size_t)l * DD, h16_);

        gemm_f16<128, 128, __half, 2><<<gFF1, 256, SM128>>>(h16_, w1_l, b1 + (size_t)l * DFFF, ff16_, DFFF, DD, 2);
        gemm_f16<64, 64, float, 3><<<gN768, 256, SM64>>>(ff16_, w2_l, b2 + (size_t)l * DD, tmp_, DD, DFFF, 1);
        ln_kernel<<<MM / 8, 256>>>(h_, tmp_, ln2_s + (size_t)l * DD, ln2_b + (size_t)l * DD, h16_);
    }

    // join: LM head waits for the side-stream conversion
    cudaStreamWaitEvent(0, ev1, 0);
    gemm_f16<128, 128, float, 2, true><<<gLM, 256, SM128>>>(h16_, lm16_, lm_b, out, VV, DD, 1);

    cudaEventDestroy(ev0);
    cudaEventDestroy(ev1);
    cudaStreamDestroy(s1);
}

// round 16
// speedup vs baseline: 1.0211x; 1.0211x over previous
#include <cuda_runtime.h>
#include <cuda_fp16.h>
#include <math.h>

// Problem constants
#define BB 2
#define SS 1024
#define DD 768
#define HH 12
#define DKK 64
#define DFFF 3072
#define VV 32000
#define LL 4
#define MM (BB*SS)       // 2048
#define NQKV (3*DD)      // 2304

// ---------------- scratch (static device globals; no allocation) -------------
__device__ float  g_h    [MM*DD];
__device__ float  g_tmp  [MM*DD];
__device__ __half g_h16  [MM*DD];
__device__ __half g_qkv16[MM*NQKV];
__device__ __half g_av16 [MM*DD];
__device__ __half g_ff16 [MM*DFFF];
// attention split-kv partials (fp32), 4 parities
__device__ float  g_avp [4*MM*DD];
__device__ float  g_den [4*MM*HH];
// fp16 weights
__device__ __half g_wqkv16[LL*DD*NQKV];   // packed [l][k][which*768+n]
__device__ __half g_wo16  [LL*DD*DD];
__device__ __half g_w116  [LL*DD*DFFF];
__device__ __half g_w216  [LL*DFFF*DD];
__device__ __half g_lm16  [DD*VV];

// ---------------- merged fp32 -> fp16 weight conversion (MLP=4) --------------
#define NQ_QKV (LL*DD*NQKV/4)
#define NQ_WO  (LL*DD*DD/4)
#define NQ_W1  (LL*DD*DFFF/4)
#define NQ_W2  (LL*DFFF*DD/4)
#define NQ_LM  (DD*VV/4)
#define NC_QKV (NQ_QKV/4)
#define NC_WO  (NQ_WO/4)
#define NC_W1  (NQ_W1/4)
#define NC_W2  (NQ_W2/4)
#define NC_LM  (NQ_LM/4)
#define NC_TOTAL (NC_QKV+NC_WO+NC_W1+NC_W2+NC_LM)

__global__ void convert_all(const float* __restrict__ Wq, const float* __restrict__ Wk,
                            const float* __restrict__ Wv, const float* __restrict__ Wo,
                            const float* __restrict__ W1, const float* __restrict__ W2,
                            const float* __restrict__ lm_W,
                            __half2* __restrict__ dqkv, __half2* __restrict__ dwo,
                            __half2* __restrict__ dw1, __half2* __restrict__ dw2,
                            __half2* __restrict__ dlm) {
    long long i = (long long)blockIdx.x * blockDim.x + threadIdx.x;
    const float* src;
    __half2* dst;
    if (i < NC_QKV) {
        long long e = i * 16;
        int c = (int)(e % NQKV);
        int k = (int)((e / NQKV) % DD);
        int l = (int)(e / ((long long)NQKV * DD));
        int which = c / DD;
        int n = c % DD;
        const float* W = (which == 0) ? Wq : (which == 1) ? Wk : Wv;
        src = W + (size_t)l * DD * DD + (size_t)k * DD + n;
        dst = dqkv + e / 2;
    }
    else if ((i -= NC_QKV) < NC_WO)      { src = Wo   + i * 16; dst = dwo + i * 8; }
    else if ((i -= NC_WO)  < NC_W1)      { src = W1   + i * 16; dst = dw1 + i * 8; }
    else if ((i -= NC_W1)  < NC_W2)      { src = W2   + i * 16; dst = dw2 + i * 8; }
    else if ((i -= NC_W2)  < NC_LM)      { src = lm_W + i * 16; dst = dlm + i * 8; }
    else return;

    float4 v0 = *reinterpret_cast<const float4*>(src + 0);
    float4 v1 = *reinterpret_cast<const float4*>(src + 4);
    float4 v2 = *reinterpret_cast<const float4*>(src + 8);
    float4 v3 = *reinterpret_cast<const float4*>(src + 12);
    __half2 h[8];
    h[0] = __floats2half2_rn(v0.x, v0.y); h[1] = __floats2half2_rn(v0.z, v0.w);
    h[2] = __floats2half2_rn(v1.x, v1.y); h[3] = __floats2half2_rn(v1.z, v1.w);
    h[4] = __floats2half2_rn(v2.x, v2.y); h[5] = __floats2half2_rn(v2.z, v2.w);
    h[6] = __floats2half2_rn(v3.x, v3.y); h[7] = __floats2half2_rn(v3.z, v3.w);
    reinterpret_cast<uint4*>(dst)[0] = reinterpret_cast<uint4*>(h)[0];
    reinterpret_cast<uint4*>(dst)[1] = reinterpret_cast<uint4*>(h)[1];
}

// ---------------- embedding + sinusoidal PE ----------------------------------
__global__ void embed_kernel(const int* __restrict__ x, const float* __restrict__ emb,
                             float* __restrict__ h, __half* __restrict__ h16) {
    int row = blockIdx.x;
    int s = row & (SS - 1);
    int tok = x[row];
    const float L2E = 13.287712379549449f;   // log2(10000)
    for (int c = threadIdx.x; c < DD; c += blockDim.x) {
        float ef = (float)(c & ~1) / (float)DD;
        float inv_sc = exp2f(-ef * L2E);
        float ang = (float)s * inv_sc;
        float pe = (c & 1) ? cosf(ang) : sinf(ang);
        float v = emb[(size_t)tok * DD + c] + pe;
        h[(size_t)row * DD + c] = v;
        h16[(size_t)row * DD + c] = __float2half(v);
    }
}

// ---------------- common PTX helpers -----------------------------------------
__device__ __forceinline__ float gelu_exact(float x) {
    return 0.5f * x * (1.0f + erff(x * 0.7071067811865476f));
}

#define CPA16(dst, src) asm volatile("cp.async.cg.shared.global [%0], [%1], 16;" :: "r"(dst), "l"(src))
#define LDSM4(r0,r1,r2,r3,addr) \
    asm volatile("ldmatrix.sync.aligned.m8n8.x4.shared.b16 {%0,%1,%2,%3},[%4];" \
                 : "=r"(r0),"=r"(r1),"=r"(r2),"=r"(r3) : "r"(addr))
#define LDSM4T(r0,r1,r2,r3,addr) \
    asm volatile("ldmatrix.sync.aligned.m8n8.x4.trans.shared.b16 {%0,%1,%2,%3},[%4];" \
                 : "=r"(r0),"=r"(r1),"=r"(r2),"=r"(r3) : "r"(addr))

__device__ __forceinline__ void mma16816(float c[4], const unsigned a[4], const unsigned b[2]) {
    asm volatile("mma.sync.aligned.m16n8k16.row.col.f32.f16.f16.f32 "
                 "{%0,%1,%2,%3},{%4,%5,%6,%7},{%8,%9},{%0,%1,%2,%3};"
                 : "+f"(c[0]), "+f"(c[1]), "+f"(c[2]), "+f"(c[3])
                 : "r"(a[0]), "r"(a[1]), "r"(a[2]), "r"(a[3]), "r"(b[0]), "r"(b[1]));
}

__device__ __forceinline__ unsigned cvta_s(const void* p) {
    return (unsigned)__cvta_generic_to_shared(p);
}
__device__ __forceinline__ unsigned packh2(float x, float y) {
    __half2 h = __floats2half2_rn(x, y);
    return *reinterpret_cast<unsigned*>(&h);
}

// ---------------- fp16 tensor-core GEMM: BMxBNxKT tiles, NSTG-stage ----------
// smem bytes = NSTG*(BM*(KT+8) + KT*(BN+8))*2
#define SMEM_GEMM_BYTES(BM,BN,KT,NSTG) ((NSTG)*((BM)*((KT)+8) + (KT)*((BN)+8)) * 2)

template<int BM, int BN, int KT, int NSTG, typename OutT>
__device__ __forceinline__ void gemm_body(
    const __half* __restrict__ A, const __half* __restrict__ B,
    const float* __restrict__ bias, OutT* __restrict__ C,
    int N, int K, int epi, int bx, int by, __half* sm)
{
    constexpr int MT = BM / 32;
    constexpr int NJ = BN / 32;
    constexpr int ASTR = KT + 8;
    constexpr int BSTR = BN + 8;
    constexpr int ABUF_H = BM * ASTR;
    constexpr int BBUF_H = KT * BSTR;

    __half* As = sm;
    __half* Bs = sm + NSTG * ABUF_H;

    int tid = threadIdx.x;
    int lane = tid & 31;
    int warp = tid >> 5;
    int wm = warp >> 2;
    int wn = warp & 3;
    int g  = lane >> 2;
    int tg = lane & 3;

    const __half* Ab = A + (size_t)by * BM * K;
    const __half* Bb = B + (size_t)bx * BN;

    float c[MT][NJ][4];
    #pragma unroll
    for (int i = 0; i < MT; i++)
        #pragma unroll
        for (int j = 0; j < NJ; j++)
            #pragma unroll
            for (int r = 0; r < 4; r++) c[i][j][r] = 0.f;

    const int T = K / KT;

    auto load_tile = [&](int kt, int buf) {
        __half* Ad = As + buf * ABUF_H;
        __half* Bd = Bs + buf * BBUF_H;
        // A: BM rows x KT halves = BM*KT/8 16B segments
        #pragma unroll
        for (int i = 0; i < BM * KT / 2048; i++) {
            int s = tid + i * 256;
            int r  = s / (KT / 8);
            int k8 = (s % (KT / 8)) * 8;
            unsigned dst = cvta_s(Ad + r * ASTR + k8);
            CPA16(dst, Ab + (size_t)r * K + kt + k8);
        }
        // B: KT rows x BN halves
        #pragma unroll
        for (int i = 0; i < KT * BN / 2048; i++) {
            int s = tid + i * 256;
            int r  = s / (BN / 8);
            int n8 = (s % (BN / 8)) * 8;
            unsigned dst = cvta_s(Bd + r * BSTR + n8);
            CPA16(dst, Bb + (size_t)(kt + r) * N + n8);
        }
    };

    #pragma unroll
    for (int s = 0; s < NSTG - 1; s++) {
        load_tile(s * KT, s);
        asm volatile("cp.async.commit_group;");
    }

    unsigned aBase = cvta_s(As + (wm * (BM / 2) + (lane & 15)) * ASTR + (lane >> 4) * 8);
    unsigned bBase = cvta_s(Bs + (lane & 15) * BSTR + wn * (BN / 4) + (lane >> 4) * 8);

    int st = 0, pb = NSTG - 1;
    for (int t = 0; t < T; t++) {
        asm volatile("cp.async.wait_group %0;" :: "n"(NSTG - 2));
        __syncthreads();

        int lt = t + NSTG - 1;
        if (lt < T) load_tile(lt * KT, pb);
        asm volatile("cp.async.commit_group;");

        unsigned aB = aBase + st * (ABUF_H * 2);
        unsigned bB = bBase + st * (BBUF_H * 2);
        if (++st == NSTG) st = 0;
        if (++pb == NSTG) pb = 0;

        #pragma unroll
        for (int kb = 0; kb < KT / 16; kb++) {
            unsigned a[MT][4], b[NJ][2];
            #pragma unroll
            for (int mt = 0; mt < MT; mt++) {
                LDSM4(a[mt][0], a[mt][1], a[mt][2], a[mt][3],
                      aB + (mt * 16 * ASTR + kb * 16) * 2);
            }
            #pragma unroll
            for (int nb = 0; nb < NJ / 2; nb++) {
                unsigned t0, t1, t2, t3;
                LDSM4T(t0, t1, t2, t3, bB + (kb * 16 * BSTR + nb * 16) * 2);
                b[2 * nb][0] = t0; b[2 * nb][1] = t1;
                b[2 * nb + 1][0] = t2; b[2 * nb + 1][1] = t3;
            }
            #pragma unroll
            for (int mt = 0; mt < MT; mt++)
                #pragma unroll
                for (int j = 0; j < NJ; j++)
                    mma16816(c[mt][j], a[mt], b[j]);
        }
    }

    int colg = bx * BN + wn * (BN / 4);
    int rowg = by * BM + wm * (BM / 2);
    #pragma unroll
    for (int mt = 0; mt < MT; mt++) {
        #pragma unroll
        for (int half = 0; half < 2; half++) {
            int row = rowg + mt * 16 + g + half * 8;
            #pragma unroll
            for (int j = 0; j < NJ; j++) {
                int col = colg + j * 8 + tg * 2;
                float v0 = c[mt][j][half * 2 + 0];
                float v1 = c[mt][j][half * 2 + 1];
                if (epi >= 1) { v0 += bias[col]; v1 += bias[col + 1]; }
                if (epi == 2) { v0 = gelu_exact(v0); v1 = gelu_exact(v1); }
                if constexpr (sizeof(OutT) == 4) {
                    float2 w; w.x = v0; w.y = v1;
                    *reinterpret_cast<float2*>((float*)C + (size_t)row * N + col) = w;
                } else {
                    *reinterpret_cast<__half2*>((__half*)C + (size_t)row * N + col) =
                        __floats2half2_rn(v0, v1);
                }
            }
        }
    }
}

template<int BM, int BN, int KT, int NSTG, typename OutT, int OCC, bool SWAPG = false>
__global__ __launch_bounds__(256, OCC)
void gemm_f16(const __half* __restrict__ A, const __half* __restrict__ B,
              const float* __restrict__ bias, OutT* __restrict__ C,
              int N, int K, int epi)
{
    extern __shared__ __half smh[];
    int bx = SWAPG ? blockIdx.y : blockIdx.x;
    int by = SWAPG ? blockIdx.x : blockIdx.y;
    gemm_body<BM, BN, KT, NSTG, OutT>(A, B, bias, C, N, K, epi, bx, by, smh);
}

// ---------------- fp16 TC causal attention, 4-way kv split -------------------
#define QSTR 72
#define KVBUF (64*QSTR)
#define ATTN_SMEM_BYTES (5 * KVBUF * 2)

__global__ __launch_bounds__(128, 4)
void attn_f16(const __half* __restrict__ qkv,
              float* __restrict__ avp, float* __restrict__ den) {
    extern __shared__ __half smh[];
    __half* Qs = smh;
    __half* Ks = smh + KVBUF;
    __half* Vs = smh + 3 * KVBUF;

    int bx = blockIdx.x;
    int qt = 15 - (bx >> 2);
    int parity = bx & 3;
    float* avP  = avp + (size_t)parity * MM * DD;
    float* denP = den + (size_t)parity * MM * HH;

    int bh = blockIdx.y;
    int b = bh / HH, hh = bh % HH;
    const __half* qb = qkv + (size_t)b * SS * NQKV + hh * DKK;
    const __half* kb = qb + DD;
    const __half* vb = qb + 2 * DD;

    int tid = threadIdx.x;
    int lane = tid & 31;
    int warp = tid >> 5;
    int g  = lane >> 2;
    int tg = lane & 3;

    int qg0 = qt * 64 + warp * 16 + g;
    int row0 = b * SS + qg0;
    const int niter = (qt >= parity) ? ((qt - parity) >> 2) + 1 : 0;

    if (niter == 0) {
        #pragma unroll
        for (int nb = 0; nb < 8; nb++) {
            int col = hh * DKK + nb * 8 + 2 * tg;
            float2 z; z.x = 0.f; z.y = 0.f;
            *reinterpret_cast<float2*>(avP + (size_t)row0 * DD + col) = z;
            *reinterpret_cast<float2*>(avP + (size_t)(row0 + 8) * DD + col) = z;
        }
        if (tg == 0) {
            denP[(size_t)row0 * HH + hh] = 0.f;
            denP[(size_t)(row0 + 8) * HH + hh] = 0.f;
        }
        return;
    }

    #pragma unroll
    for (int i = 0; i < 4; i++) {
        int s = tid + i * 128;
        int r = s >> 3;
        int c8 = (s & 7) * 8;
        CPA16(cvta_s(Qs + r * QSTR + c8), qb + (size_t)(qt * 64 + r) * NQKV + c8);
    }
    auto load_kv = [&](int kt, int buf) {
        __half* Kd = Ks + buf * KVBUF;
        __half* Vd = Vs + buf * KVBUF;
        #pragma unroll
        for (int i = 0; i < 4; i++) {
            int s = tid + i * 128;
            int r = s >> 3;
            int c8 = (s & 7) * 8;
            CPA16(cvta_s(Kd + r * QSTR + c8), kb + (size_t)(kt * 64 + r) * NQKV + c8);
            CPA16(cvta_s(Vd + r * QSTR + c8), vb + (size_t)(kt * 64 + r) * NQKV + c8);
        }
    };
    load_kv(parity, 0);
    asm volatile("cp.async.commit_group;");

    float oacc[8][4];
    #pragma unroll
    for (int i = 0; i < 8; i++)
        #pragma unroll
        for (int j = 0; j < 4; j++) oacc[i][j] = 0.f;
    float den0 = 0.f, den1 = 0.f;

    unsigned qAddr = cvta_s(Qs + (warp * 16 + (lane & 15)) * QSTR + (lane >> 4) * 8);

    for (int it = 0; it < niter; it++) {
        int kt = parity + 4 * it;
        asm volatile("cp.async.wait_group 0;");
        __syncthreads();
        if (it + 1 < niter) {
            load_kv(kt + 4, (it + 1) & 1);
            asm volatile("cp.async.commit_group;");
        }
        const __half* Kb_ = Ks + (it & 1) * KVBUF;
        const __half* Vb_ = Vs + (it & 1) * KVBUF;

        float s[8][4];
        #pragma unroll
        for (int i = 0; i < 8; i++)
            #pragma unroll
            for (int j = 0; j < 4; j++) s[i][j] = 0.f;

        #pragma unroll
        for (int kbk = 0; kbk < 4; kbk++) {
            unsigned a[4];
            LDSM4(a[0], a[1], a[2], a[3], qAddr + kbk * 16 * 2);
            #pragma unroll
            for (int nb2 = 0; nb2 < 4; nb2++) {
                unsigned r0, r1, r2, r3;
                LDSM4(r0, r1, r2, r3,
                      cvta_s(Kb_ + (nb2 * 16 + (lane & 15)) * QSTR + kbk * 16 + (lane >> 4) * 8));
                unsigned b0[2] = { r0, r2 };
                unsigned b1[2] = { r1, r3 };
                mma16816(s[2 * nb2],     a, b0);
                mma16816(s[2 * nb2 + 1], a, b1);
            }
        }

        bool diag = (kt == qt);
        #pragma unroll
        for (int nb = 0; nb < 8; nb++) {
            int kg = kt * 64 + nb * 8 + 2 * tg;
            float e0 = (!diag || kg     < qg0)     ? __expf(s[nb][0] * 0.125f) : 0.f;
            float e1 = (!diag || kg + 1 < qg0)     ? __expf(s[nb][1] * 0.125f) : 0.f;
            float e2 = (!diag || kg     < qg0 + 8) ? __expf(s[nb][2] * 0.125f) : 0.f;
            float e3 = (!diag || kg + 1 < qg0 + 8) ? __expf(s[nb][3] * 0.125f) : 0.f;
            s[nb][0] = e0; s[nb][1] = e1; s[nb][2] = e2; s[nb][3] = e3;
            den0 += e0 + e1;
            den1 += e2 + e3;
        }

        #pragma unroll
        for (int kbk = 0; kbk < 4; kbk++) {
            unsigned a[4];
            a[0] = packh2(s[2 * kbk][0],     s[2 * kbk][1]);
            a[1] = packh2(s[2 * kbk][2],     s[2 * kbk][3]);
            a[2] = packh2(s[2 * kbk + 1][0], s[2 * kbk + 1][1]);
            a[3] = packh2(s[2 * kbk + 1][2], s[2 * kbk + 1][3]);
            #pragma unroll
            for (int nb2 = 0; nb2 < 4; nb2++) {
                unsigned t0, t1, t2, t3;
                LDSM4T(t0, t1, t2, t3,
                       cvta_s(Vb_ + (kbk * 16 + (lane & 15)) * QSTR + nb2 * 16 + (lane >> 4) * 8));
                unsigned b0[2] = { t0, t1 };
                unsigned b1[2] = { t2, t3 };
                mma16816(oacc[2 * nb2],     a, b0);
                mma16816(oacc[2 * nb2 + 1], a, b1);
            }
        }
    }

    den0 += __shfl_xor_sync(0xffffffffu, den0, 1);
    den0 += __shfl_xor_sync(0xffffffffu, den0, 2);
    den1 += __shfl_xor_sync(0xffffffffu, den1, 1);
    den1 += __shfl_xor_sync(0xffffffffu, den1, 2);

    #pragma unroll
    for (int nb = 0; nb < 8; nb++) {
        int col = hh * DKK + nb * 8 + 2 * tg;
        float2 w0; w0.x = oacc[nb][0]; w0.y = oacc[nb][1];
        float2 w1; w1.x = oacc[nb][2]; w1.y = oacc[nb][3];
        *reinterpret_cast<float2*>(avP + (size_t)row0 * DD + col) = w0;
        *reinterpret_cast<float2*>(avP + (size_t)(row0 + 8) * DD + col) = w1;
    }
    if (tg == 0) {
        denP[(size_t)row0 * HH + hh] = den0;
        denP[(size_t)(row0 + 8) * HH + hh] = den1;
    }
}

// combine partials: av16 = (Σp)/(Σd + 1e-9)
__global__ void attn_norm(const float* __restrict__ p, const float* __restrict__ d,
                          __half* __restrict__ o) {
    int row = blockIdx.x;
    size_t base = (size_t)row * DD;
    for (int c = threadIdx.x; c < DD; c += blockDim.x) {
        int hh = c >> 6;
        size_t di = (size_t)row * HH + hh;
        float den = d[di] + d[MM*HH + di] + d[2*(size_t)MM*HH + di] + d[3*(size_t)MM*HH + di] + 1e-9f;
        float num = p[base + c] + p[MM*(size_t)DD + base + c]
                  + p[2*(size_t)MM*DD + base + c] + p[3*(size_t)MM*DD + base + c];
        o[base + c] = __float2half(num / den);
    }
}

// ---------------- warp-per-row residual-add + LayerNorm ----------------------
__global__ __launch_bounds__(256)
void ln_kernel(float* __restrict__ h, const float* __restrict__ delta,
               const float* __restrict__ gs, const float* __restrict__ gb,
               __half* __restrict__ h16) {
    int lane = threadIdx.x & 31;
    int row = blockIdx.x * 8 + (threadIdx.x >> 5);
    size_t base = (size_t)row * DD;
    const float4* hp = reinterpret_cast<const float4*>(h + base);
    const float4* dp = reinterpret_cast<const float4*>(delta + base);

    float4 v[6];
    float sum = 0.f;
    #pragma unroll
    for (int t = 0; t < 6; t++) {
        float4 a = hp[lane + t * 32];
        float4 b = dp[lane + t * 32];
        v[t].x = a.x + b.x; v[t].y = a.y + b.y;
        v[t].z = a.z + b.z; v[t].w = a.w + b.w;
        sum += v[t].x + v[t].y + v[t].z + v[t].w;
    }
    #pragma unroll
    for (int o = 16; o; o >>= 1) sum += __shfl_xor_sync(0xffffffffu, sum, o);
    float mean = sum * (1.0f / 768.0f);

    float sq = 0.f;
    #pragma unroll
    for (int t = 0; t < 6; t++) {
        float dx = v[t].x - mean, dy = v[t].y - mean;
        float dz = v[t].z - mean, dw = v[t].w - mean;
        sq += dx * dx + dy * dy + dz * dz + dw * dw;
    }
    #pragma unroll
    for (int o = 16; o; o >>= 1) sq += __shfl_xor_sync(0xffffffffu, sq, o);
    float inv = rsqrtf(sq * (1.0f / 768.0f) + 1e-5f);

    float4* ho = reinterpret_cast<float4*>(h + base);
    #pragma unroll
    for (int t = 0; t < 6; t++) {
        int c4 = (lane + t * 32) * 4;
        float4 gsv = *reinterpret_cast<const float4*>(gs + c4);
        float4 gbv = *reinterpret_cast<const float4*>(gb + c4);
        float4 r;
        r.x = (v[t].x - mean) * inv * gsv.x + gbv.x;
        r.y = (v[t].y - mean) * inv * gsv.y + gbv.y;
        r.z = (v[t].z - mean) * inv * gsv.z + gbv.z;
        r.w = (v[t].w - mean) * inv * gsv.w + gbv.w;
        ho[lane + t * 32] = r;
        __half2 p0 = __floats2half2_rn(r.x, r.y);
        __half2 p1 = __floats2half2_rn(r.z, r.w);
        __half2* h16o = reinterpret_cast<__half2*>(h16 + base + c4);
        h16o[0] = p0;
        h16o[1] = p1;
    }
}

// ---------------- launcher ---------------------------------------------------
extern "C" void kernel_launch(void* const* d_in, const int* in_sizes, int n_in,
                              void* d_out, int out_size) {
    const int*   x     = (const int*)  d_in[0];
    const float* emb   = (const float*)d_in[1];
    const float* Wq    = (const float*)d_in[2];
    const float* Wk    = (const float*)d_in[3];
    const float* Wv    = (const float*)d_in[4];
    const float* Wo    = (const float*)d_in[5];
    const float* ln1_s = (const float*)d_in[6];
    const float* ln1_b = (const float*)d_in[7];
    const float* W1    = (const float*)d_in[8];
    const float* b1    = (const float*)d_in[9];
    const float* W2    = (const float*)d_in[10];
    const float* b2    = (const float*)d_in[11];
    const float* ln2_s = (const float*)d_in[12];
    const float* ln2_b = (const float*)d_in[13];
    const float* lm_W  = (const float*)d_in[14];
    const float* lm_b  = (const float*)d_in[15];
    float* out = (float*)d_out;

    float *h_, *tmp_, *avp_, *den_;
    __half *h16_, *qkv16_, *av16_, *ff16_, *wqkv16_, *wo16_, *w116_, *w216_, *lm16_;
    cudaGetSymbolAddress((void**)&h_,     g_h);
    cudaGetSymbolAddress((void**)&tmp_,   g_tmp);
    cudaGetSymbolAddress((void**)&avp_,   g_avp);
    cudaGetSymbolAddress((void**)&den_,   g_den);
    cudaGetSymbolAddress((void**)&h16_,   g_h16);
    cudaGetSymbolAddress((void**)&qkv16_, g_qkv16);
    cudaGetSymbolAddress((void**)&av16_,  g_av16);
    cudaGetSymbolAddress((void**)&ff16_,  g_ff16);
    cudaGetSymbolAddress((void**)&wqkv16_, g_wqkv16);
    cudaGetSymbolAddress((void**)&wo16_,   g_wo16);
    cudaGetSymbolAddress((void**)&w116_,   g_w116);
    cudaGetSymbolAddress((void**)&w216_,   g_w216);
    cudaGetSymbolAddress((void**)&lm16_,   g_lm16);

    const int SMBIG = SMEM_GEMM_BYTES(128, 128, 64, 3);   // 107520
    const int SM64  = SMEM_GEMM_BYTES(64, 64, 32, 4);     // 38912
    cudaFuncSetAttribute(attn_f16, cudaFuncAttributeMaxDynamicSharedMemorySize, ATTN_SMEM_BYTES);
    cudaFuncSetAttribute((const void*)gemm_f16<128, 128, 64, 3, float, 2, true>,   cudaFuncAttributeMaxDynamicSharedMemorySize, SMBIG);
    cudaFuncSetAttribute((const void*)gemm_f16<128, 128, 64, 3, __half, 2, false>, cudaFuncAttributeMaxDynamicSharedMemorySize, SMBIG);
    cudaFuncSetAttribute((const void*)gemm_f16<64, 64, 32, 4, float, 3, false>,    cudaFuncAttributeMaxDynamicSharedMemorySize, SM64);

    // ---- merged weight conversion (one launch, MLP=4) ----
    convert_all<<<(int)((NC_TOTAL + 255) / 256), 256>>>(
        Wq, Wk, Wv, Wo, W1, W2, lm_W,
        (__half2*)wqkv16_, (__half2*)wo16_, (__half2*)w116_,
        (__half2*)w216_, (__half2*)lm16_);

    embed_kernel<<<MM, 256>>>(x, emb, h_, h16_);

    dim3 gQKV(NQKV / 128, MM / 128);    // (18,16)
    dim3 gN768(DD / 64, MM / 64);       // (12,32) 64x64 tiles
    dim3 gFF1(DFFF / 128, MM / 128);    // (24,16)
    dim3 gLM(MM / 128, VV / 128);       // (16,250) swapped: M fastest
    dim3 gAttn(64, BB * HH);            // (64,24): (qt, 4-way parity)

    for (int l = 0; l < LL; l++) {
        const __half* wqkv_l = wqkv16_ + (size_t)l * DD * NQKV;
        const __half* wo_l   = wo16_   + (size_t)l * DD * DD;
        const __half* w1_l   = w116_   + (size_t)l * DD * DFFF;
        const __half* w2_l   = w216_   + (size_t)l * DFFF * DD;

        gemm_f16<128, 128, 64, 3, __half, 2><<<gQKV, 256, SMBIG>>>(h16_, wqkv_l, nullptr, qkv16_, NQKV, DD, 0);

        attn_f16<<<gAttn, 128, ATTN_SMEM_BYTES>>>(qkv16_, avp_, den_);
        attn_norm<<<MM, 256>>>(avp_, den_, av16_);

        gemm_f16<64, 64, 32, 4, float, 3><<<gN768, 256, SM64>>>(av16_, wo_l, nullptr, tmp_, DD, DD, 0);
        ln_kernel<<<MM / 8, 256>>>(h_, tmp_, ln1_s + (size_t)l * DD, ln1_b + (size_t)l * DD, h16_);

        gemm_f16<128, 128, 64, 3, __half, 2><<<gFF1, 256, SMBIG>>>(h16_, w1_l, b1 + (size_t)l * DFFF, ff16_, DFFF, DD, 2);
        gemm_f16<64, 64, 32, 4, float, 3><<<gN768, 256, SM64>>>(ff16_, w2_l, b2 + (size_t)l * DD, tmp_, DD, DFFF, 1);
        ln_kernel<<<MM / 8, 256>>>(h_, tmp_, ln2_s + (size_t)l * DD, ln2_b + (size_t)l * DD, h16_);
    }

    gemm_f16<128, 128, 64, 3, float, 2, true><<<gLM, 256, SMBIG>>>(h16_, lm16_, lm_b, out, VV, DD, 1);
}